// round 8
// baseline (speedup 1.0000x reference)
#include <cuda_runtime.h>
#include <cuda_fp16.h>
#include <cstdint>

#define NPTS 100000
#define BSZ  8
#define CIMG 512
#define CPT  256
#define IMH  48
#define IMW  160
#define HW   (IMH*IMW)      /* 7680  */
#define NPIX (BSZ*HW)       /* 61440 */

// Scratch (device globals; no allocation in kernel_launch)
__device__ __half g_Wh[CPT * CIMG];                  // align_w in fp16, row-major (256,512)
__device__ __half g_pix[(size_t)NPIX * CPT];         // channel-last projected pixels, fp16

// ---------------------------------------------------------------------------
// Kernel 0: convert align_w (f32) -> fp16
// ---------------------------------------------------------------------------
__global__ void convW_kernel(const float* __restrict__ W) {
    int i = blockIdx.x * blockDim.x + threadIdx.x;
    if (i < CPT * CIMG) g_Wh[i] = __float2half_rn(W[i]);
}

// ---------------------------------------------------------------------------
// Kernel 1: per-batch GEMM  pix_b(7680x256) = G_b^T(7680x512) @ W^T(512x256)
//   BM=64 x BN=256, BK=32, 8 warps (warp tile 32x64), occ=2.
//   A path: LDG.128 f32 -> regs -> cvt fp16 -> STS (double-buffered Ah),
//           pipelined one tile ahead in registers (8 floats/thread).
//   B path: cp.async 3-stage fp16.
//   2 syncthreads per tile (was 3 in R6 + full smem f32 round trip).
// ---------------------------------------------------------------------------
#define BM 64
#define BN 256
#define BK 32
#define BSTG 3

#define B_ROW_H   (BK + 8)                 /* 40 halves, 80B row */
#define B_STAGE_H (BN * B_ROW_H)           /* 10240 halves = 20480 B */
#define AH_ROW_H  (BM + 8)                 /* 72 halves */
#define AH_STAGE_H (BK * AH_ROW_H)         /* 2304 halves = 4608 B */
#define SMEM_TOTAL (2 * AH_STAGE_H * 2 + BSTG * B_STAGE_H * 2)   /* 70656 B */

__device__ __forceinline__ void cp16(void* s, const void* g) {
    uint32_t sa = (uint32_t)__cvta_generic_to_shared(s);
    asm volatile("cp.async.cg.shared.global [%0], [%1], 16;" :: "r"(sa), "l"(g));
}

__global__ __launch_bounds__(256, 2)
void gemm_pix_kernel(const float* __restrict__ img) {
    extern __shared__ char smem_raw[];
    __half* Ah = reinterpret_cast<__half*>(smem_raw);                    // [2][BK][AH_ROW_H]
    __half* Bs = reinterpret_cast<__half*>(smem_raw + 2 * AH_STAGE_H * 2); // [BSTG][BN][B_ROW_H]

    const int b  = blockIdx.z;
    const int p0 = blockIdx.x * BM;
    const float* gA = img + (size_t)b * CIMG * HW;

    const int tid  = threadIdx.x;
    const int lane = tid & 31;
    const int warp = tid >> 5;
    const int wm   = warp & 1;    // m offset wm*32
    const int wn   = warp >> 1;   // n offset wn*64

    float acc[2][8][4];
    #pragma unroll
    for (int i = 0; i < 2; i++)
        #pragma unroll
        for (int j = 0; j < 8; j++)
            #pragma unroll
            for (int k = 0; k < 4; k++) acc[i][j][k] = 0.f;

    // A mapping: 2 chunks/thread. chunk idx = tid + i*256 (0..511):
    //   k = idx>>4 (0..31), mc = (idx&15)*4 (0..60)
    int ak_[2], am_[2];
    #pragma unroll
    for (int i = 0; i < 2; i++) {
        int idx = tid + i * 256;
        ak_[i] = idx >> 4;
        am_[i] = (idx & 15) << 2;
    }
    // B mapping: 4 chunks/thread. n = idx>>2, kc = (idx&3)*8

    float4 areg[2];

    // Prologue: A tile 0 into regs; B tiles 0..2 via cp.async
    #pragma unroll
    for (int i = 0; i < 2; i++)
        areg[i] = *reinterpret_cast<const float4*>(gA + (size_t)ak_[i] * HW + p0 + am_[i]);
    #pragma unroll
    for (int s = 0; s < BSTG; s++) {
        const int kt = s * BK;
        #pragma unroll
        for (int i = 0; i < 4; i++) {
            int idx = tid + i * 256;
            int n = idx >> 2, kc = (idx & 3) << 3;
            cp16(&Bs[s * B_STAGE_H + n * B_ROW_H + kc],
                 &g_Wh[n * CIMG + kt + kc]);
        }
        asm volatile("cp.async.commit_group;");
    }

    const int NT = CIMG / BK;   // 16
    for (int t = 0; t < NT; t++) {
        const int ast = t & 1;
        const int bst = t % BSTG;

        // STS current A tile (regs -> fp16 smem)
        #pragma unroll
        for (int i = 0; i < 2; i++) {
            __half2 h0 = __floats2half2_rn(areg[i].x, areg[i].y);
            __half2 h1 = __floats2half2_rn(areg[i].z, areg[i].w);
            __half2* dst = reinterpret_cast<__half2*>(&Ah[ast * AH_STAGE_H + ak_[i] * AH_ROW_H + am_[i]]);
            dst[0] = h0;
            dst[1] = h1;
        }
        // Issue next A tile's LDGs (consumed next iteration)
        if (t + 1 < NT) {
            const int kt = (t + 1) * BK;
            #pragma unroll
            for (int i = 0; i < 2; i++)
                areg[i] = *reinterpret_cast<const float4*>(
                    gA + (size_t)(kt + ak_[i]) * HW + p0 + am_[i]);
        }

        asm volatile("cp.async.wait_group %0;" :: "n"(BSTG - 1));
        __syncthreads();

        #pragma unroll
        for (int ks = 0; ks < BK; ks += 16) {
            uint32_t af[2][4];
            uint32_t bfr[8][2];
            {
                int jj = lane >> 3, r = lane & 7;
                int m_off = (jj & 1) * 8, k_off = (jj >> 1) * 8;
                #pragma unroll
                for (int mt = 0; mt < 2; mt++) {
                    uint32_t addr = (uint32_t)__cvta_generic_to_shared(
                        &Ah[ast * AH_STAGE_H + (ks + k_off + r) * AH_ROW_H + wm * 32 + mt * 16 + m_off]);
                    asm volatile("ldmatrix.sync.aligned.m8n8.x4.trans.shared.b16 {%0,%1,%2,%3}, [%4];"
                                 : "=r"(af[mt][0]), "=r"(af[mt][1]), "=r"(af[mt][2]), "=r"(af[mt][3])
                                 : "r"(addr));
                }
                int jb = (lane >> 3) & 1;
                #pragma unroll
                for (int nt = 0; nt < 8; nt++) {
                    uint32_t addr = (uint32_t)__cvta_generic_to_shared(
                        &Bs[bst * B_STAGE_H + (wn * 64 + nt * 8 + r) * B_ROW_H + ks + jb * 8]);
                    asm volatile("ldmatrix.sync.aligned.m8n8.x2.shared.b16 {%0,%1}, [%2];"
                                 : "=r"(bfr[nt][0]), "=r"(bfr[nt][1])
                                 : "r"(addr));
                }
            }
            #pragma unroll
            for (int mt = 0; mt < 2; mt++)
                #pragma unroll
                for (int nt = 0; nt < 8; nt++) {
                    asm volatile("mma.sync.aligned.m16n8k16.row.col.f32.f16.f16.f32 "
                                 "{%0,%1,%2,%3}, {%4,%5,%6,%7}, {%8,%9}, {%0,%1,%2,%3};"
                                 : "+f"(acc[mt][nt][0]), "+f"(acc[mt][nt][1]),
                                   "+f"(acc[mt][nt][2]), "+f"(acc[mt][nt][3])
                                 : "r"(af[mt][0]), "r"(af[mt][1]), "r"(af[mt][2]), "r"(af[mt][3]),
                                   "r"(bfr[nt][0]), "r"(bfr[nt][1]));
                }
        }
        __syncthreads();   // slot reads done before refill/overwrite

        // Refill B slot with tile t+BSTG (empty commit keeps group count aligned)
        if (t + BSTG < NT) {
            const int kt = (t + BSTG) * BK;
            #pragma unroll
            for (int i = 0; i < 4; i++) {
                int idx = tid + i * 256;
                int n = idx >> 2, kc = (idx & 3) << 3;
                cp16(&Bs[bst * B_STAGE_H + n * B_ROW_H + kc],
                     &g_Wh[n * CIMG + kt + kc]);
            }
        }
        asm volatile("cp.async.commit_group;");
    }

    // Epilogue: write fp16 channel-last pix
    const int mrow = lane >> 2;
    const int ncol = (lane & 3) * 2;
    #pragma unroll
    for (int mt = 0; mt < 2; mt++) {
        #pragma unroll
        for (int nt = 0; nt < 8; nt++) {
            int m = wm * 32 + mt * 16 + mrow;
            int n = wn * 64 + nt * 8 + ncol;
            size_t base = ((size_t)(b * HW + p0 + m)) * CPT + n;
            *reinterpret_cast<__half2*>(&g_pix[base]) =
                __floats2half2_rn(acc[mt][nt][0], acc[mt][nt][1]);
            *reinterpret_cast<__half2*>(&g_pix[base + 8 * CPT]) =
                __floats2half2_rn(acc[mt][nt][2], acc[mt][nt][3]);
        }
    }
}

// ---------------------------------------------------------------------------
// Kernel 2: per-point projection + bilinear combine of precomputed pix + bias
//   One warp per point, 8 channels per lane. Corner loads are unconditional
//   (clamped addresses, weight 0 for invalid) so all 4 LDGs batch -> MLP 4.
// ---------------------------------------------------------------------------
__global__ void fuse_kernel(const float* __restrict__ pf,
                            const float* __restrict__ centers,
                            const float* __restrict__ P2,
                            const float* __restrict__ R0,
                            const float* __restrict__ Tr,
                            const float* __restrict__ bias,
                            const int*   __restrict__ bidx,
                            float* __restrict__ out) {
    const int gw   = (blockIdx.x * blockDim.x + threadIdx.x) >> 5;
    const int lane = threadIdx.x & 31;
    if (gw >= NPTS) return;
    const int n = gw;
    const int b = bidx[n];

    const float px = centers[n * 3 + 0];
    const float py = centers[n * 3 + 1];
    const float pz = centers[n * 3 + 2];
    const float* tr = Tr + b * 16;
    const float* r0 = R0 + b * 16;
    const float* p2 = P2 + b * 12;

    float cam[4], rect[4], im[3];
    #pragma unroll
    for (int i = 0; i < 4; i++)
        cam[i] = tr[i*4+0]*px + tr[i*4+1]*py + tr[i*4+2]*pz + tr[i*4+3];
    #pragma unroll
    for (int i = 0; i < 4; i++)
        rect[i] = r0[i*4+0]*cam[0] + r0[i*4+1]*cam[1] + r0[i*4+2]*cam[2] + r0[i*4+3]*cam[3];
    #pragma unroll
    for (int i = 0; i < 3; i++)
        im[i] = p2[i*4+0]*rect[0] + p2[i*4+1]*rect[1] + p2[i*4+2]*rect[2] + p2[i*4+3]*rect[3];

    const float zc    = im[2];
    const float depth = fmaxf(zc, 1e-5f);
    const float u     = im[0] / depth;
    const float v     = im[1] / depth;
    const bool valid  = (zc > 0.f) && (u >= 0.f) && (u < (float)IMW) && (v >= 0.f) && (v < (float)IMH);

    const float x0f = floorf(u), y0f = floorf(v);
    const float wx1 = u - x0f, wx0 = 1.f - wx1;
    const float wy1 = v - y0f, wy0 = 1.f - wy1;
    const int xi0 = (int)x0f, yi0 = (int)y0f;

    const float cw[4] = {wx0 * wy0, wx1 * wy0, wx0 * wy1, wx1 * wy1};
    float wgt[4];
    const __half* rp[4];
    #pragma unroll
    for (int k = 0; k < 4; k++) {
        int xi = xi0 + (k & 1);
        int yi = yi0 + (k >> 1);
        bool inb = (xi >= 0) && (xi <= IMW - 1) && (yi >= 0) && (yi <= IMH - 1);
        wgt[k] = (valid && inb) ? cw[k] : 0.f;
        int xc = min(max(xi, 0), IMW - 1);
        int yc = min(max(yi, 0), IMH - 1);
        rp[k] = &g_pix[((size_t)((b * IMH + yc) * IMW + xc)) * CPT];
    }

    const int c = lane * 8;                 // 8 channels per lane
    // Unconditional batched corner loads (MLP 4)
    uint4 raw[4];
    #pragma unroll
    for (int k = 0; k < 4; k++)
        raw[k] = *reinterpret_cast<const uint4*>(rp[k] + c);

    float a[8];
    #pragma unroll
    for (int j = 0; j < 8; j++) a[j] = 0.f;
    #pragma unroll
    for (int k = 0; k < 4; k++) {
        const __half2* h = reinterpret_cast<const __half2*>(&raw[k]);
        #pragma unroll
        for (int j = 0; j < 4; j++) {
            float2 f = __half22float2(h[j]);
            a[2*j]   = fmaf(wgt[k], f.x, a[2*j]);
            a[2*j+1] = fmaf(wgt[k], f.y, a[2*j+1]);
        }
    }

    const float* pfrow = pf + (size_t)n * CPT + c;
    float*       orow  = out + (size_t)n * CPT + c;
    #pragma unroll
    for (int h = 0; h < 2; h++) {
        float4 pfv = *reinterpret_cast<const float4*>(pfrow + h * 4);
        float4 bv  = *reinterpret_cast<const float4*>(bias + c + h * 4);
        float4 o;
        o.x = pfv.x + (a[4*h+0] + bv.x);
        o.y = pfv.y + (a[4*h+1] + bv.y);
        o.z = pfv.z + (a[4*h+2] + bv.z);
        o.w = pfv.w + (a[4*h+3] + bv.w);
        *reinterpret_cast<float4*>(orow + h * 4) = o;
    }
}

// ---------------------------------------------------------------------------
// Launch
// ---------------------------------------------------------------------------
extern "C" void kernel_launch(void* const* d_in, const int* in_sizes, int n_in,
                              void* d_out, int out_size) {
    const float* point_feat = (const float*)d_in[0];
    const float* centers    = (const float*)d_in[1];
    const float* img_feat   = (const float*)d_in[2];
    const float* P2         = (const float*)d_in[3];
    const float* R0         = (const float*)d_in[4];
    const float* Tr         = (const float*)d_in[5];
    const float* align_w    = (const float*)d_in[6];
    const float* align_b    = (const float*)d_in[7];
    const int*   bidx       = (const int*)d_in[8];
    float* out = (float*)d_out;

    // Idempotent attribute set (not an allocation; safe under graph capture)
    cudaFuncSetAttribute(gemm_pix_kernel,
                         cudaFuncAttributeMaxDynamicSharedMemorySize, SMEM_TOTAL);

    convW_kernel<<<(CPT * CIMG + 255) / 256, 256>>>(align_w);
    gemm_pix_kernel<<<dim3(HW / BM, 1, BSZ), 256, SMEM_TOTAL>>>(img_feat);
    fuse_kernel<<<(NPTS + 7) / 8, 256>>>(point_feat, centers, P2, R0, Tr, align_b, bidx, out);
}

// round 9
// speedup vs baseline: 1.2372x; 1.2372x over previous
#include <cuda_runtime.h>
#include <cuda_fp16.h>
#include <cstdint>

#define NPTS 100000
#define BSZ  8
#define CIMG 512
#define CPT  256
#define IMH  48
#define IMW  160
#define HW   (IMH*IMW)      /* 7680  */
#define NPIX (BSZ*HW)       /* 61440 */

// Scratch (device globals; no allocation in kernel_launch)
__device__ __half g_Wh[CPT * CIMG];                  // align_w in fp16, row-major (256,512)
__device__ __half g_pix[(size_t)NPIX * CPT];         // channel-last projected pixels, fp16

// ---------------------------------------------------------------------------
// Kernel 0: convert align_w (f32) -> fp16
// ---------------------------------------------------------------------------
__global__ void convW_kernel(const float* __restrict__ W) {
    int i = blockIdx.x * blockDim.x + threadIdx.x;
    if (i < CPT * CIMG) g_Wh[i] = __float2half_rn(W[i]);
#if __CUDA_ARCH__ >= 900
    cudaTriggerProgrammaticLaunchCompletion();
#endif
}

// ---------------------------------------------------------------------------
// Kernel 1: per-batch GEMM  pix_b(7680x256) = G_b^T(7680x512) @ W^T(512x256)
//   R6 structure (proven): cp.async 3-stage, BM=64 x BN=256 (A read once),
//   A staged f32 + on-chip convert hop, warp tile 32x64, occ=2.
//   PDL: A prologue issued before grid-sync on convW; triggers fuse launch.
// ---------------------------------------------------------------------------
#define BM 64
#define BN 256
#define BK 32
#define STAGES 3

#define A_STAGE_F     (BK * BM)                /* 2048 f32 = 8192 B  */
#define B_ROW_H       (BK + 8)                 /* 40 halves, 80B row */
#define B_STAGE_H     (BN * B_ROW_H)           /* 10240 halves = 20480 B */
#define AH_ROW_H      (BM + 8)                 /* 72 halves */
#define SMEM_TOTAL (STAGES * A_STAGE_F * 4 + STAGES * B_STAGE_H * 2 + BK * AH_ROW_H * 2)

__device__ __forceinline__ void cp16(void* s, const void* g) {
    uint32_t sa = (uint32_t)__cvta_generic_to_shared(s);
    asm volatile("cp.async.cg.shared.global [%0], [%1], 16;" :: "r"(sa), "l"(g));
}

__global__ __launch_bounds__(256, 2)
void gemm_pix_kernel(const float* __restrict__ img) {
    extern __shared__ char smem_raw[];
    float*  Af = reinterpret_cast<float*>(smem_raw);                           // [STAGES][BK][BM]
    __half* Bs = reinterpret_cast<__half*>(smem_raw + STAGES * A_STAGE_F * 4); // [STAGES][BN][B_ROW_H]
    __half* Ah = reinterpret_cast<__half*>(smem_raw + STAGES * A_STAGE_F * 4
                                           + STAGES * B_STAGE_H * 2);          // [BK][AH_ROW_H]

    const int b  = blockIdx.z;
    const int p0 = blockIdx.x * BM;
    const float* gA = img + (size_t)b * CIMG * HW;

    const int tid  = threadIdx.x;
    const int lane = tid & 31;
    const int warp = tid >> 5;
    const int wm   = warp & 1;    // m offset wm*32
    const int wn   = warp >> 1;   // n offset wn*64

    float acc[2][8][4];
    #pragma unroll
    for (int i = 0; i < 2; i++)
        #pragma unroll
        for (int j = 0; j < 8; j++)
            #pragma unroll
            for (int k = 0; k < 4; k++) acc[i][j][k] = 0.f;

    // Prologue part 1: A tiles (img — independent of convW) for all stages
    #pragma unroll
    for (int s = 0; s < STAGES; s++) {
        const int kt = s * BK;
        #pragma unroll
        for (int i = 0; i < 2; i++) {
            int idx = tid + i * 256;
            int k  = idx >> 4, mc = (idx & 15) << 2;
            cp16(&Af[s * A_STAGE_F + k * BM + mc],
                 gA + (size_t)(kt + k) * HW + p0 + mc);
        }
    }
#if __CUDA_ARCH__ >= 900
    // Release the fuse launch early; wait for convW before touching g_Wh.
    cudaTriggerProgrammaticLaunchCompletion();
    cudaGridDependencySynchronize();
#endif
    // Prologue part 2: B tiles (g_Wh) — one commit per stage.
    // Group 0 contains all A cp.asyncs + B stage 0; groups 1,2 contain B only.
    #pragma unroll
    for (int s = 0; s < STAGES; s++) {
        const int kt = s * BK;
        #pragma unroll
        for (int i = 0; i < 4; i++) {
            int idx = tid + i * 256;
            int n = idx >> 2, kc = (idx & 3) << 3;
            cp16(&Bs[s * B_STAGE_H + n * B_ROW_H + kc],
                 &g_Wh[n * CIMG + kt + kc]);
        }
        asm volatile("cp.async.commit_group;");
    }

    const int NT = CIMG / BK;   // 16
    for (int t = 0; t < NT; t++) {
        asm volatile("cp.async.wait_group %0;" :: "n"(STAGES - 1));
        __syncthreads();
        const int slot = t % STAGES;

        // Convert f32 stage -> fp16 Ah (512 float4, 2/thread)
        #pragma unroll
        for (int i = 0; i < 2; i++) {
            int idx = tid + i * 256;
            int k = idx >> 4, m4 = (idx & 15) << 2;
            float4 v = *reinterpret_cast<const float4*>(&Af[slot * A_STAGE_F + k * BM + m4]);
            *reinterpret_cast<__half2*>(&Ah[k * AH_ROW_H + m4])     = __floats2half2_rn(v.x, v.y);
            *reinterpret_cast<__half2*>(&Ah[k * AH_ROW_H + m4 + 2]) = __floats2half2_rn(v.z, v.w);
        }
        __syncthreads();

        #pragma unroll
        for (int ks = 0; ks < BK; ks += 16) {
            uint32_t af[2][4];
            uint32_t bfr[8][2];
            {
                int jj = lane >> 3, r = lane & 7;
                int m_off = (jj & 1) * 8, k_off = (jj >> 1) * 8;
                #pragma unroll
                for (int mt = 0; mt < 2; mt++) {
                    uint32_t addr = (uint32_t)__cvta_generic_to_shared(
                        &Ah[(ks + k_off + r) * AH_ROW_H + wm * 32 + mt * 16 + m_off]);
                    asm volatile("ldmatrix.sync.aligned.m8n8.x4.trans.shared.b16 {%0,%1,%2,%3}, [%4];"
                                 : "=r"(af[mt][0]), "=r"(af[mt][1]), "=r"(af[mt][2]), "=r"(af[mt][3])
                                 : "r"(addr));
                }
                int jb = (lane >> 3) & 1;
                #pragma unroll
                for (int nt = 0; nt < 8; nt++) {
                    uint32_t addr = (uint32_t)__cvta_generic_to_shared(
                        &Bs[slot * B_STAGE_H + (wn * 64 + nt * 8 + r) * B_ROW_H + ks + jb * 8]);
                    asm volatile("ldmatrix.sync.aligned.m8n8.x2.shared.b16 {%0,%1}, [%2];"
                                 : "=r"(bfr[nt][0]), "=r"(bfr[nt][1])
                                 : "r"(addr));
                }
            }
            #pragma unroll
            for (int mt = 0; mt < 2; mt++)
                #pragma unroll
                for (int nt = 0; nt < 8; nt++) {
                    asm volatile("mma.sync.aligned.m16n8k16.row.col.f32.f16.f16.f32 "
                                 "{%0,%1,%2,%3}, {%4,%5,%6,%7}, {%8,%9}, {%0,%1,%2,%3};"
                                 : "+f"(acc[mt][nt][0]), "+f"(acc[mt][nt][1]),
                                   "+f"(acc[mt][nt][2]), "+f"(acc[mt][nt][3])
                                 : "r"(af[mt][0]), "r"(af[mt][1]), "r"(af[mt][2]), "r"(af[mt][3]),
                                   "r"(bfr[nt][0]), "r"(bfr[nt][1]));
                }
        }
        __syncthreads();   // all reads of this slot done before refill

        // Refill this slot with tile t+STAGES
        if (t + STAGES < NT) {
            const int kt = (t + STAGES) * BK;
            #pragma unroll
            for (int i = 0; i < 2; i++) {
                int idx = tid + i * 256;
                int k  = idx >> 4, mc = (idx & 15) << 2;
                cp16(&Af[slot * A_STAGE_F + k * BM + mc],
                     gA + (size_t)(kt + k) * HW + p0 + mc);
            }
            #pragma unroll
            for (int i = 0; i < 4; i++) {
                int idx = tid + i * 256;
                int n = idx >> 2, kc = (idx & 3) << 3;
                cp16(&Bs[slot * B_STAGE_H + n * B_ROW_H + kc],
                     &g_Wh[n * CIMG + kt + kc]);
            }
        }
        asm volatile("cp.async.commit_group;");
    }

    // Epilogue: write fp16 channel-last pix
    const int mrow = lane >> 2;
    const int ncol = (lane & 3) * 2;
    #pragma unroll
    for (int mt = 0; mt < 2; mt++) {
        #pragma unroll
        for (int nt = 0; nt < 8; nt++) {
            int m = wm * 32 + mt * 16 + mrow;
            int n = wn * 64 + nt * 8 + ncol;
            size_t base = ((size_t)(b * HW + p0 + m)) * CPT + n;
            *reinterpret_cast<__half2*>(&g_pix[base]) =
                __floats2half2_rn(acc[mt][nt][0], acc[mt][nt][1]);
            *reinterpret_cast<__half2*>(&g_pix[base + 8 * CPT]) =
                __floats2half2_rn(acc[mt][nt][2], acc[mt][nt][3]);
        }
    }
}

// ---------------------------------------------------------------------------
// Kernel 2 (PDL secondary): projection + pf/bias loads BEFORE grid-sync
//   (overlaps the GEMM tail), then pix gather + combine + store after.
// ---------------------------------------------------------------------------
__global__ void fuse_kernel(const float* __restrict__ pf,
                            const float* __restrict__ centers,
                            const float* __restrict__ P2,
                            const float* __restrict__ R0,
                            const float* __restrict__ Tr,
                            const float* __restrict__ bias,
                            const int*   __restrict__ bidx,
                            float* __restrict__ out) {
    const int gw   = (blockIdx.x * blockDim.x + threadIdx.x) >> 5;
    const int lane = threadIdx.x & 31;
    if (gw >= NPTS) return;
    const int n = gw;
    const int b = bidx[n];

    const float px = centers[n * 3 + 0];
    const float py = centers[n * 3 + 1];
    const float pz = centers[n * 3 + 2];
    const float* tr = Tr + b * 16;
    const float* r0 = R0 + b * 16;
    const float* p2 = P2 + b * 12;

    float cam[4], rect[4], im[3];
    #pragma unroll
    for (int i = 0; i < 4; i++)
        cam[i] = tr[i*4+0]*px + tr[i*4+1]*py + tr[i*4+2]*pz + tr[i*4+3];
    #pragma unroll
    for (int i = 0; i < 4; i++)
        rect[i] = r0[i*4+0]*cam[0] + r0[i*4+1]*cam[1] + r0[i*4+2]*cam[2] + r0[i*4+3]*cam[3];
    #pragma unroll
    for (int i = 0; i < 3; i++)
        im[i] = p2[i*4+0]*rect[0] + p2[i*4+1]*rect[1] + p2[i*4+2]*rect[2] + p2[i*4+3]*rect[3];

    const float zc    = im[2];
    const float depth = fmaxf(zc, 1e-5f);
    const float u     = im[0] / depth;
    const float v     = im[1] / depth;
    const bool valid  = (zc > 0.f) && (u >= 0.f) && (u < (float)IMW) && (v >= 0.f) && (v < (float)IMH);

    const float x0f = floorf(u), y0f = floorf(v);
    const float wx1 = u - x0f, wx0 = 1.f - wx1;
    const float wy1 = v - y0f, wy0 = 1.f - wy1;
    const int xi0 = (int)x0f, yi0 = (int)y0f;

    const float cw[4] = {wx0 * wy0, wx1 * wy0, wx0 * wy1, wx1 * wy1};
    float wgt[4];
    const __half* rp[4];
    #pragma unroll
    for (int k = 0; k < 4; k++) {
        int xi = xi0 + (k & 1);
        int yi = yi0 + (k >> 1);
        bool inb = (xi >= 0) && (xi <= IMW - 1) && (yi >= 0) && (yi <= IMH - 1);
        wgt[k] = (valid && inb) ? cw[k] : 0.f;
        int xc = min(max(xi, 0), IMW - 1);
        int yc = min(max(yi, 0), IMH - 1);
        rp[k] = &g_pix[((size_t)((b * IMH + yc) * IMW + xc)) * CPT];
    }

    const int c = lane * 8;                 // 8 channels per lane
    // Independent-of-GEMM loads issued BEFORE the dependency sync
    const float* pfrow = pf + (size_t)n * CPT + c;
    float4 pfv0 = *reinterpret_cast<const float4*>(pfrow);
    float4 pfv1 = *reinterpret_cast<const float4*>(pfrow + 4);
    float4 bv0  = *reinterpret_cast<const float4*>(bias + c);
    float4 bv1  = *reinterpret_cast<const float4*>(bias + c + 4);

#if __CUDA_ARCH__ >= 900
    cudaGridDependencySynchronize();   // wait for GEMM's g_pix
#endif

    // Unconditional batched corner loads (clamped addresses, wgt 0 if invalid)
    uint4 raw[4];
    #pragma unroll
    for (int k = 0; k < 4; k++)
        raw[k] = *reinterpret_cast<const uint4*>(rp[k] + c);

    float a[8];
    #pragma unroll
    for (int j = 0; j < 8; j++) a[j] = 0.f;
    #pragma unroll
    for (int k = 0; k < 4; k++) {
        const __half2* h = reinterpret_cast<const __half2*>(&raw[k]);
        #pragma unroll
        for (int j = 0; j < 4; j++) {
            float2 f = __half22float2(h[j]);
            a[2*j]   = fmaf(wgt[k], f.x, a[2*j]);
            a[2*j+1] = fmaf(wgt[k], f.y, a[2*j+1]);
        }
    }

    float* orow = out + (size_t)n * CPT + c;
    float4 o0, o1;
    o0.x = pfv0.x + (a[0] + bv0.x);
    o0.y = pfv0.y + (a[1] + bv0.y);
    o0.z = pfv0.z + (a[2] + bv0.z);
    o0.w = pfv0.w + (a[3] + bv0.w);
    o1.x = pfv1.x + (a[4] + bv1.x);
    o1.y = pfv1.y + (a[5] + bv1.y);
    o1.z = pfv1.z + (a[6] + bv1.z);
    o1.w = pfv1.w + (a[7] + bv1.w);
    *reinterpret_cast<float4*>(orow)     = o0;
    *reinterpret_cast<float4*>(orow + 4) = o1;
}

// ---------------------------------------------------------------------------
// Launch (PDL chain: convW -> gemm -> fuse)
// ---------------------------------------------------------------------------
extern "C" void kernel_launch(void* const* d_in, const int* in_sizes, int n_in,
                              void* d_out, int out_size) {
    const float* point_feat = (const float*)d_in[0];
    const float* centers    = (const float*)d_in[1];
    const float* img_feat   = (const float*)d_in[2];
    const float* P2         = (const float*)d_in[3];
    const float* R0         = (const float*)d_in[4];
    const float* Tr         = (const float*)d_in[5];
    const float* align_w    = (const float*)d_in[6];
    const float* align_b    = (const float*)d_in[7];
    const int*   bidx       = (const int*)d_in[8];
    float* out = (float*)d_out;

    // Idempotent attribute set (not an allocation; safe under graph capture)
    cudaFuncSetAttribute(gemm_pix_kernel,
                         cudaFuncAttributeMaxDynamicSharedMemorySize, SMEM_TOTAL);

    convW_kernel<<<(CPT * CIMG + 255) / 256, 256>>>(align_w);

    cudaLaunchAttribute pdl[1];
    pdl[0].id = cudaLaunchAttributeProgrammaticStreamSerialization;
    pdl[0].val.programmaticStreamSerializationAllowed = 1;

    {   // GEMM as PDL secondary of convW
        cudaLaunchConfig_t cfg = {};
        cfg.gridDim  = dim3(HW / BM, 1, BSZ);
        cfg.blockDim = dim3(256, 1, 1);
        cfg.dynamicSmemBytes = SMEM_TOTAL;
        cfg.stream = 0;
        cfg.attrs = pdl;
        cfg.numAttrs = 1;
        cudaLaunchKernelEx(&cfg, gemm_pix_kernel, img_feat);
    }
    {   // fuse as PDL secondary of GEMM
        cudaLaunchConfig_t cfg = {};
        cfg.gridDim  = dim3((NPTS + 7) / 8, 1, 1);
        cfg.blockDim = dim3(256, 1, 1);
        cfg.dynamicSmemBytes = 0;
        cfg.stream = 0;
        cfg.attrs = pdl;
        cfg.numAttrs = 1;
        cudaLaunchKernelEx(&cfg, fuse_kernel,
                           point_feat, centers, P2, R0, Tr, align_b, bidx, out);
    }
}

// round 10
// speedup vs baseline: 1.2606x; 1.0189x over previous
#include <cuda_runtime.h>
#include <cuda_fp16.h>
#include <cstdint>

#define NPTS 100000
#define BSZ  8
#define CIMG 512
#define CPT  256
#define IMH  48
#define IMW  160
#define HW   (IMH*IMW)      /* 7680  */
#define NPIX (BSZ*HW)       /* 61440 */

// Scratch (device globals; no allocation in kernel_launch)
__device__ __half g_Wh[CPT * CIMG];                  // align_w in fp16, row-major (256,512)
__device__ __half g_pix[(size_t)NPIX * CPT];         // channel-last projected pixels, fp16

// ---------------------------------------------------------------------------
// Kernel 0: convert align_w (f32) -> fp16
// ---------------------------------------------------------------------------
__global__ void convW_kernel(const float* __restrict__ W) {
    int i = blockIdx.x * blockDim.x + threadIdx.x;
    if (i < CPT * CIMG) g_Wh[i] = __float2half_rn(W[i]);
}

// ---------------------------------------------------------------------------
// Kernel 1: per-batch GEMM  pix_b(7680x256) = G_b^T(7680x512) @ W^T(512x256)
//   cp.async 3-stage, BM=64 x BN=256 (A read once), occ=2.
//   Convert-ahead: tile t+1's f32->fp16 hop overlaps tile t's ldmatrix+MMA;
//   Ah double-buffered; 2 barriers per tile (was 3).
// ---------------------------------------------------------------------------
#define BM 64
#define BN 256
#define BK 32
#define STAGES 3

#define A_STAGE_F     (BK * BM)                /* 2048 f32 = 8192 B  */
#define B_ROW_H       (BK + 8)                 /* 40 halves, 80B row */
#define B_STAGE_H     (BN * B_ROW_H)           /* 10240 halves = 20480 B */
#define AH_ROW_H      (BM + 8)                 /* 72 halves */
#define AH_STAGE_H    (BK * AH_ROW_H)          /* 2304 halves = 4608 B */
#define SMEM_TOTAL (STAGES * A_STAGE_F * 4 + STAGES * B_STAGE_H * 2 + 2 * AH_STAGE_H * 2)

__device__ __forceinline__ void cp16(void* s, const void* g) {
    uint32_t sa = (uint32_t)__cvta_generic_to_shared(s);
    asm volatile("cp.async.cg.shared.global [%0], [%1], 16;" :: "r"(sa), "l"(g));
}

__global__ __launch_bounds__(256, 2)
void gemm_pix_kernel(const float* __restrict__ img) {
    extern __shared__ char smem_raw[];
    float*  Af = reinterpret_cast<float*>(smem_raw);                           // [STAGES][BK][BM]
    __half* Bs = reinterpret_cast<__half*>(smem_raw + STAGES * A_STAGE_F * 4); // [STAGES][BN][B_ROW_H]
    __half* Ah = reinterpret_cast<__half*>(smem_raw + STAGES * A_STAGE_F * 4
                                           + STAGES * B_STAGE_H * 2);          // [2][BK][AH_ROW_H]

    const int b  = blockIdx.z;
    const int p0 = blockIdx.x * BM;
    const float* gA = img + (size_t)b * CIMG * HW;

    const int tid  = threadIdx.x;
    const int lane = tid & 31;
    const int warp = tid >> 5;
    const int wm   = warp & 1;    // m offset wm*32
    const int wn   = warp >> 1;   // n offset wn*64

    float acc[2][8][4];
    #pragma unroll
    for (int i = 0; i < 2; i++)
        #pragma unroll
        for (int j = 0; j < 8; j++)
            #pragma unroll
            for (int k = 0; k < 4; k++) acc[i][j][k] = 0.f;

    // Per-thread mappings
    //   A: 2 chunks/thread: k = idx>>4 (0..31), mc = (idx&15)*4
    //   B: 4 chunks/thread: n = idx>>2, kc = (idx&3)*8
    int ak_[2], am_[2];
    #pragma unroll
    for (int i = 0; i < 2; i++) {
        int idx = tid + i * 256;
        ak_[i] = idx >> 4;
        am_[i] = (idx & 15) << 2;
    }

    // Prologue: issue stages 0..2 (one commit per stage: A slot s + B slot s)
    #pragma unroll
    for (int s = 0; s < STAGES; s++) {
        const int kt = s * BK;
        #pragma unroll
        for (int i = 0; i < 2; i++)
            cp16(&Af[s * A_STAGE_F + ak_[i] * BM + am_[i]],
                 gA + (size_t)(kt + ak_[i]) * HW + p0 + am_[i]);
        #pragma unroll
        for (int i = 0; i < 4; i++) {
            int idx = tid + i * 256;
            int n = idx >> 2, kc = (idx & 3) << 3;
            cp16(&Bs[s * B_STAGE_H + n * B_ROW_H + kc],
                 &g_Wh[n * CIMG + kt + kc]);
        }
        asm volatile("cp.async.commit_group;");
    }

    // Prologue convert: tile 0 -> Ah[0]
    asm volatile("cp.async.wait_group %0;" :: "n"(STAGES - 1));
    __syncthreads();
    #pragma unroll
    for (int i = 0; i < 2; i++) {
        float4 v = *reinterpret_cast<const float4*>(&Af[ak_[i] * BM + am_[i]]);
        __half2* dst = reinterpret_cast<__half2*>(&Ah[ak_[i] * AH_ROW_H + am_[i]]);
        dst[0] = __floats2half2_rn(v.x, v.y);
        dst[1] = __floats2half2_rn(v.z, v.w);
    }

    const int NT = CIMG / BK;   // 16
    for (int t = 0; t < NT; t++) {
        const int slot = t % STAGES;
        asm volatile("cp.async.wait_group %0;" :: "n"(1));
        __syncthreads();   // publishes: tile t/t+1 cp.async data, Ah[t&1] convert

        // Convert-ahead: tile t+1 -> Ah[(t+1)&1]  (overlaps MMA below)
        if (t + 1 < NT) {
            const int ns = (t + 1) % STAGES;
            const int na = (t + 1) & 1;
            #pragma unroll
            for (int i = 0; i < 2; i++) {
                float4 v = *reinterpret_cast<const float4*>(
                    &Af[ns * A_STAGE_F + ak_[i] * BM + am_[i]]);
                __half2* dst = reinterpret_cast<__half2*>(
                    &Ah[na * AH_STAGE_H + ak_[i] * AH_ROW_H + am_[i]]);
                dst[0] = __floats2half2_rn(v.x, v.y);
                dst[1] = __floats2half2_rn(v.z, v.w);
            }
        }

        const int ab = (t & 1) * AH_STAGE_H;
        #pragma unroll
        for (int ks = 0; ks < BK; ks += 16) {
            uint32_t af[2][4];
            uint32_t bfr[8][2];
            {
                int jj = lane >> 3, r = lane & 7;
                int m_off = (jj & 1) * 8, k_off = (jj >> 1) * 8;
                #pragma unroll
                for (int mt = 0; mt < 2; mt++) {
                    uint32_t addr = (uint32_t)__cvta_generic_to_shared(
                        &Ah[ab + (ks + k_off + r) * AH_ROW_H + wm * 32 + mt * 16 + m_off]);
                    asm volatile("ldmatrix.sync.aligned.m8n8.x4.trans.shared.b16 {%0,%1,%2,%3}, [%4];"
                                 : "=r"(af[mt][0]), "=r"(af[mt][1]), "=r"(af[mt][2]), "=r"(af[mt][3])
                                 : "r"(addr));
                }
                int jb = (lane >> 3) & 1;
                #pragma unroll
                for (int nt = 0; nt < 8; nt++) {
                    uint32_t addr = (uint32_t)__cvta_generic_to_shared(
                        &Bs[slot * B_STAGE_H + (wn * 64 + nt * 8 + r) * B_ROW_H + ks + jb * 8]);
                    asm volatile("ldmatrix.sync.aligned.m8n8.x2.shared.b16 {%0,%1}, [%2];"
                                 : "=r"(bfr[nt][0]), "=r"(bfr[nt][1])
                                 : "r"(addr));
                }
            }
            #pragma unroll
            for (int mt = 0; mt < 2; mt++)
                #pragma unroll
                for (int nt = 0; nt < 8; nt++) {
                    asm volatile("mma.sync.aligned.m16n8k16.row.col.f32.f16.f16.f32 "
                                 "{%0,%1,%2,%3}, {%4,%5,%6,%7}, {%8,%9}, {%0,%1,%2,%3};"
                                 : "+f"(acc[mt][nt][0]), "+f"(acc[mt][nt][1]),
                                   "+f"(acc[mt][nt][2]), "+f"(acc[mt][nt][3])
                                 : "r"(af[mt][0]), "r"(af[mt][1]), "r"(af[mt][2]), "r"(af[mt][3]),
                                   "r"(bfr[nt][0]), "r"(bfr[nt][1]));
                }
        }
        __syncthreads();   // MMA + convert-ahead done before slot refill

        if (t + STAGES < NT) {
            const int kt = (t + STAGES) * BK;
            #pragma unroll
            for (int i = 0; i < 2; i++)
                cp16(&Af[slot * A_STAGE_F + ak_[i] * BM + am_[i]],
                     gA + (size_t)(kt + ak_[i]) * HW + p0 + am_[i]);
            #pragma unroll
            for (int i = 0; i < 4; i++) {
                int idx = tid + i * 256;
                int n = idx >> 2, kc = (idx & 3) << 3;
                cp16(&Bs[slot * B_STAGE_H + n * B_ROW_H + kc],
                     &g_Wh[n * CIMG + kt + kc]);
            }
        }
        asm volatile("cp.async.commit_group;");  // empty commit at tail keeps counts aligned
    }

    // Epilogue: write fp16 channel-last pix
    const int mrow = lane >> 2;
    const int ncol = (lane & 3) * 2;
    #pragma unroll
    for (int mt = 0; mt < 2; mt++) {
        #pragma unroll
        for (int nt = 0; nt < 8; nt++) {
            int m = wm * 32 + mt * 16 + mrow;
            int n = wn * 64 + nt * 8 + ncol;
            size_t base = ((size_t)(b * HW + p0 + m)) * CPT + n;
            *reinterpret_cast<__half2*>(&g_pix[base]) =
                __floats2half2_rn(acc[mt][nt][0], acc[mt][nt][1]);
            *reinterpret_cast<__half2*>(&g_pix[base + 8 * CPT]) =
                __floats2half2_rn(acc[mt][nt][2], acc[mt][nt][3]);
        }
    }
}

// ---------------------------------------------------------------------------
// Kernel 2: per-point projection + bilinear combine of precomputed pix + bias
//   One warp per point, 8 channels per lane; unconditional batched corner
//   loads (clamped addresses, zero weights) -> MLP 4.
// ---------------------------------------------------------------------------
__global__ void fuse_kernel(const float* __restrict__ pf,
                            const float* __restrict__ centers,
                            const float* __restrict__ P2,
                            const float* __restrict__ R0,
                            const float* __restrict__ Tr,
                            const float* __restrict__ bias,
                            const int*   __restrict__ bidx,
                            float* __restrict__ out) {
    const int gw   = (blockIdx.x * blockDim.x + threadIdx.x) >> 5;
    const int lane = threadIdx.x & 31;
    if (gw >= NPTS) return;
    const int n = gw;
    const int b = bidx[n];

    const float px = centers[n * 3 + 0];
    const float py = centers[n * 3 + 1];
    const float pz = centers[n * 3 + 2];
    const float* tr = Tr + b * 16;
    const float* r0 = R0 + b * 16;
    const float* p2 = P2 + b * 12;

    float cam[4], rect[4], im[3];
    #pragma unroll
    for (int i = 0; i < 4; i++)
        cam[i] = tr[i*4+0]*px + tr[i*4+1]*py + tr[i*4+2]*pz + tr[i*4+3];
    #pragma unroll
    for (int i = 0; i < 4; i++)
        rect[i] = r0[i*4+0]*cam[0] + r0[i*4+1]*cam[1] + r0[i*4+2]*cam[2] + r0[i*4+3]*cam[3];
    #pragma unroll
    for (int i = 0; i < 3; i++)
        im[i] = p2[i*4+0]*rect[0] + p2[i*4+1]*rect[1] + p2[i*4+2]*rect[2] + p2[i*4+3]*rect[3];

    const float zc    = im[2];
    const float depth = fmaxf(zc, 1e-5f);
    const float u     = im[0] / depth;
    const float v     = im[1] / depth;
    const bool valid  = (zc > 0.f) && (u >= 0.f) && (u < (float)IMW) && (v >= 0.f) && (v < (float)IMH);

    const float x0f = floorf(u), y0f = floorf(v);
    const float wx1 = u - x0f, wx0 = 1.f - wx1;
    const float wy1 = v - y0f, wy0 = 1.f - wy1;
    const int xi0 = (int)x0f, yi0 = (int)y0f;

    const float cw[4] = {wx0 * wy0, wx1 * wy0, wx0 * wy1, wx1 * wy1};
    float wgt[4];
    const __half* rp[4];
    #pragma unroll
    for (int k = 0; k < 4; k++) {
        int xi = xi0 + (k & 1);
        int yi = yi0 + (k >> 1);
        bool inb = (xi >= 0) && (xi <= IMW - 1) && (yi >= 0) && (yi <= IMH - 1);
        wgt[k] = (valid && inb) ? cw[k] : 0.f;
        int xc = min(max(xi, 0), IMW - 1);
        int yc = min(max(yi, 0), IMH - 1);
        rp[k] = &g_pix[((size_t)((b * IMH + yc) * IMW + xc)) * CPT];
    }

    const int c = lane * 8;                 // 8 channels per lane
    uint4 raw[4];
    #pragma unroll
    for (int k = 0; k < 4; k++)
        raw[k] = *reinterpret_cast<const uint4*>(rp[k] + c);

    float a[8];
    #pragma unroll
    for (int j = 0; j < 8; j++) a[j] = 0.f;
    #pragma unroll
    for (int k = 0; k < 4; k++) {
        const __half2* h = reinterpret_cast<const __half2*>(&raw[k]);
        #pragma unroll
        for (int j = 0; j < 4; j++) {
            float2 f = __half22float2(h[j]);
            a[2*j]   = fmaf(wgt[k], f.x, a[2*j]);
            a[2*j+1] = fmaf(wgt[k], f.y, a[2*j+1]);
        }
    }

    const float* pfrow = pf + (size_t)n * CPT + c;
    float*       orow  = out + (size_t)n * CPT + c;
    #pragma unroll
    for (int h = 0; h < 2; h++) {
        float4 pfv = *reinterpret_cast<const float4*>(pfrow + h * 4);
        float4 bv  = *reinterpret_cast<const float4*>(bias + c + h * 4);
        float4 o;
        o.x = pfv.x + (a[4*h+0] + bv.x);
        o.y = pfv.y + (a[4*h+1] + bv.y);
        o.z = pfv.z + (a[4*h+2] + bv.z);
        o.w = pfv.w + (a[4*h+3] + bv.w);
        *reinterpret_cast<float4*>(orow + h * 4) = o;
    }
}

// ---------------------------------------------------------------------------
// Launch
// ---------------------------------------------------------------------------
extern "C" void kernel_launch(void* const* d_in, const int* in_sizes, int n_in,
                              void* d_out, int out_size) {
    const float* point_feat = (const float*)d_in[0];
    const float* centers    = (const float*)d_in[1];
    const float* img_feat   = (const float*)d_in[2];
    const float* P2         = (const float*)d_in[3];
    const float* R0         = (const float*)d_in[4];
    const float* Tr         = (const float*)d_in[5];
    const float* align_w    = (const float*)d_in[6];
    const float* align_b    = (const float*)d_in[7];
    const int*   bidx       = (const int*)d_in[8];
    float* out = (float*)d_out;

    // Idempotent attribute set (not an allocation; safe under graph capture)
    cudaFuncSetAttribute(gemm_pix_kernel,
                         cudaFuncAttributeMaxDynamicSharedMemorySize, SMEM_TOTAL);

    convW_kernel<<<(CPT * CIMG + 255) / 256, 256>>>(align_w);
    gemm_pix_kernel<<<dim3(HW / BM, 1, BSZ), 256, SMEM_TOTAL>>>(img_feat);
    fuse_kernel<<<(NPTS + 7) / 8, 256>>>(point_feat, centers, P2, R0, Tr, align_b, bidx, out);
}

// round 12
// speedup vs baseline: 1.2776x; 1.0135x over previous
#include <cuda_runtime.h>
#include <cuda_fp16.h>
#include <cstdint>

#define NPTS 100000
#define BSZ  8
#define CIMG 512
#define CPT  256
#define IMH  48
#define IMW  160
#define HW   (IMH*IMW)      /* 7680  */
#define NPIX (BSZ*HW)       /* 61440 */

// Scratch (device globals; no allocation in kernel_launch)
__device__ __half g_Wh[CPT * CIMG];                  // align_w in fp16, row-major (256,512)
__device__ __half g_pix[(size_t)NPIX * CPT];         // channel-last projected pixels, fp16

// ---------------------------------------------------------------------------
// Kernel 0: convert align_w (f32) -> fp16
// ---------------------------------------------------------------------------
__global__ void convW_kernel(const float* __restrict__ W) {
    int i = blockIdx.x * blockDim.x + threadIdx.x;
    if (i < CPT * CIMG) g_Wh[i] = __float2half_rn(W[i]);
}

// ---------------------------------------------------------------------------
// Kernel 1: per-batch GEMM  pix_b(7680x256) = G_b^T(7680x512) @ W^T(512x256)
//   cp.async 3-stage, BM=64 x BN=256 (A read once), occ=2.
//   Convert-ahead double-buffered Ah, 2 barriers/tile.
//   B fragments via ldmatrix.x4 (2 n-tiles per instr) -> half the B-feed issues.
// ---------------------------------------------------------------------------
#define BM 64
#define BN 256
#define BK 32
#define STAGES 3

#define A_STAGE_F     (BK * BM)                /* 2048 f32 = 8192 B  */
#define B_ROW_H       (BK + 8)                 /* 40 halves, 80B row */
#define B_STAGE_H     (BN * B_ROW_H)           /* 10240 halves = 20480 B */
#define AH_ROW_H      (BM + 8)                 /* 72 halves */
#define AH_STAGE_H    (BK * AH_ROW_H)          /* 2304 halves = 4608 B */
#define SMEM_TOTAL (STAGES * A_STAGE_F * 4 + STAGES * B_STAGE_H * 2 + 2 * AH_STAGE_H * 2)

__device__ __forceinline__ void cp16(void* s, const void* g) {
    uint32_t sa = (uint32_t)__cvta_generic_to_shared(s);
    asm volatile("cp.async.cg.shared.global [%0], [%1], 16;" :: "r"(sa), "l"(g));
}

__global__ __launch_bounds__(256, 2)
void gemm_pix_kernel(const float* __restrict__ img) {
    extern __shared__ char smem_raw[];
    float*  Af = reinterpret_cast<float*>(smem_raw);                           // [STAGES][BK][BM]
    __half* Bs = reinterpret_cast<__half*>(smem_raw + STAGES * A_STAGE_F * 4); // [STAGES][BN][B_ROW_H]
    __half* Ah = reinterpret_cast<__half*>(smem_raw + STAGES * A_STAGE_F * 4
                                           + STAGES * B_STAGE_H * 2);          // [2][BK][AH_ROW_H]

    const int b  = blockIdx.z;
    const int p0 = blockIdx.x * BM;
    const float* gA = img + (size_t)b * CIMG * HW;

    const int tid  = threadIdx.x;
    const int lane = tid & 31;
    const int warp = tid >> 5;
    const int wm   = warp & 1;    // m offset wm*32
    const int wn   = warp >> 1;   // n offset wn*64

    float acc[2][8][4];
    #pragma unroll
    for (int i = 0; i < 2; i++)
        #pragma unroll
        for (int j = 0; j < 8; j++)
            #pragma unroll
            for (int k = 0; k < 4; k++) acc[i][j][k] = 0.f;

    int ak_[2], am_[2];
    #pragma unroll
    for (int i = 0; i < 2; i++) {
        int idx = tid + i * 256;
        ak_[i] = idx >> 4;
        am_[i] = (idx & 15) << 2;
    }

    // Prologue: issue stages 0..2 (one commit per stage: A slot s + B slot s)
    #pragma unroll
    for (int s = 0; s < STAGES; s++) {
        const int kt = s * BK;
        #pragma unroll
        for (int i = 0; i < 2; i++)
            cp16(&Af[s * A_STAGE_F + ak_[i] * BM + am_[i]],
                 gA + (size_t)(kt + ak_[i]) * HW + p0 + am_[i]);
        #pragma unroll
        for (int i = 0; i < 4; i++) {
            int idx = tid + i * 256;
            int n = idx >> 2, kc = (idx & 3) << 3;
            cp16(&Bs[s * B_STAGE_H + n * B_ROW_H + kc],
                 &g_Wh[n * CIMG + kt + kc]);
        }
        asm volatile("cp.async.commit_group;");
    }

    // Prologue convert: tile 0 -> Ah[0]
    asm volatile("cp.async.wait_group %0;" :: "n"(STAGES - 1));
    __syncthreads();
    #pragma unroll
    for (int i = 0; i < 2; i++) {
        float4 v = *reinterpret_cast<const float4*>(&Af[ak_[i] * BM + am_[i]]);
        __half2* dst = reinterpret_cast<__half2*>(&Ah[ak_[i] * AH_ROW_H + am_[i]]);
        dst[0] = __floats2half2_rn(v.x, v.y);
        dst[1] = __floats2half2_rn(v.z, v.w);
    }

    const int NT = CIMG / BK;   // 16
    for (int t = 0; t < NT; t++) {
        const int slot = t % STAGES;
        asm volatile("cp.async.wait_group %0;" :: "n"(1));
        __syncthreads();   // publishes: tile t/t+1 cp.async data, Ah[t&1] convert

        // Convert-ahead: tile t+1 -> Ah[(t+1)&1]  (overlaps MMA below)
        if (t + 1 < NT) {
            const int ns = (t + 1) % STAGES;
            const int na = (t + 1) & 1;
            #pragma unroll
            for (int i = 0; i < 2; i++) {
                float4 v = *reinterpret_cast<const float4*>(
                    &Af[ns * A_STAGE_F + ak_[i] * BM + am_[i]]);
                __half2* dst = reinterpret_cast<__half2*>(
                    &Ah[na * AH_STAGE_H + ak_[i] * AH_ROW_H + am_[i]]);
                dst[0] = __floats2half2_rn(v.x, v.y);
                dst[1] = __floats2half2_rn(v.z, v.w);
            }
        }

        const int ab = (t & 1) * AH_STAGE_H;
        #pragma unroll
        for (int ks = 0; ks < BK; ks += 16) {
            uint32_t af[2][4];
            uint32_t bfr[8][2];
            {
                int jj = lane >> 3, r = lane & 7;
                int m_off = (jj & 1) * 8, k_off = (jj >> 1) * 8;
                #pragma unroll
                for (int mt = 0; mt < 2; mt++) {
                    uint32_t addr = (uint32_t)__cvta_generic_to_shared(
                        &Ah[ab + (ks + k_off + r) * AH_ROW_H + wm * 32 + mt * 16 + m_off]);
                    asm volatile("ldmatrix.sync.aligned.m8n8.x4.trans.shared.b16 {%0,%1,%2,%3}, [%4];"
                                 : "=r"(af[mt][0]), "=r"(af[mt][1]), "=r"(af[mt][2]), "=r"(af[mt][3])
                                 : "r"(addr));
                }
                // B: one x4 per 2 adjacent n-tiles:
                //   mat0=(2p,k-lo) mat1=(2p,k-hi) mat2=(2p+1,k-lo) mat3=(2p+1,k-hi)
                #pragma unroll
                for (int p = 0; p < 4; p++) {
                    uint32_t addr = (uint32_t)__cvta_generic_to_shared(
                        &Bs[slot * B_STAGE_H
                            + (wn * 64 + (p * 2 + (jj >> 1)) * 8 + r) * B_ROW_H
                            + ks + (jj & 1) * 8]);
                    asm volatile("ldmatrix.sync.aligned.m8n8.x4.shared.b16 {%0,%1,%2,%3}, [%4];"
                                 : "=r"(bfr[2*p][0]), "=r"(bfr[2*p][1]),
                                   "=r"(bfr[2*p+1][0]), "=r"(bfr[2*p+1][1])
                                 : "r"(addr));
                }
            }
            #pragma unroll
            for (int mt = 0; mt < 2; mt++)
                #pragma unroll
                for (int nt = 0; nt < 8; nt++) {
                    asm volatile("mma.sync.aligned.m16n8k16.row.col.f32.f16.f16.f32 "
                                 "{%0,%1,%2,%3}, {%4,%5,%6,%7}, {%8,%9}, {%0,%1,%2,%3};"
                                 : "+f"(acc[mt][nt][0]), "+f"(acc[mt][nt][1]),
                                   "+f"(acc[mt][nt][2]), "+f"(acc[mt][nt][3])
                                 : "r"(af[mt][0]), "r"(af[mt][1]), "r"(af[mt][2]), "r"(af[mt][3]),
                                   "r"(bfr[nt][0]), "r"(bfr[nt][1]));
                }
        }
        __syncthreads();   // MMA + convert-ahead done before slot refill

        if (t + STAGES < NT) {
            const int kt = (t + STAGES) * BK;
            #pragma unroll
            for (int i = 0; i < 2; i++)
                cp16(&Af[slot * A_STAGE_F + ak_[i] * BM + am_[i]],
                     gA + (size_t)(kt + ak_[i]) * HW + p0 + am_[i]);
            #pragma unroll
            for (int i = 0; i < 4; i++) {
                int idx = tid + i * 256;
                int n = idx >> 2, kc = (idx & 3) << 3;
                cp16(&Bs[slot * B_STAGE_H + n * B_ROW_H + kc],
                     &g_Wh[n * CIMG + kt + kc]);
            }
        }
        asm volatile("cp.async.commit_group;");
    }

    // Epilogue: write fp16 channel-last pix
    const int mrow = lane >> 2;
    const int ncol = (lane & 3) * 2;
    #pragma unroll
    for (int mt = 0; mt < 2; mt++) {
        #pragma unroll
        for (int nt = 0; nt < 8; nt++) {
            int m = wm * 32 + mt * 16 + mrow;
            int n = wn * 64 + nt * 8 + ncol;
            size_t base = ((size_t)(b * HW + p0 + m)) * CPT + n;
            *reinterpret_cast<__half2*>(&g_pix[base]) =
                __floats2half2_rn(acc[mt][nt][0], acc[mt][nt][1]);
            *reinterpret_cast<__half2*>(&g_pix[base + 8 * CPT]) =
                __floats2half2_rn(acc[mt][nt][2], acc[mt][nt][3]);
        }
    }
}

// ---------------------------------------------------------------------------
// Kernel 2: per-point projection + bilinear combine. TWO points per warp:
//   8 batched pix corner loads in flight (MLP 8), 8 channels per lane.
// ---------------------------------------------------------------------------
__global__ void fuse_kernel(const float* __restrict__ pf,
                            const float* __restrict__ centers,
                            const float* __restrict__ P2,
                            const float* __restrict__ R0,
                            const float* __restrict__ Tr,
                            const float* __restrict__ bias,
                            const int*   __restrict__ bidx,
                            float* __restrict__ out) {
    const int gw   = (blockIdx.x * blockDim.x + threadIdx.x) >> 5;
    const int lane = threadIdx.x & 31;
    const int n0   = gw * 2;
    if (n0 >= NPTS) return;           // NPTS even -> n0+1 always valid

    const int c = lane * 8;           // 8 channels per lane
    float4 bv0 = *reinterpret_cast<const float4*>(bias + c);
    float4 bv1 = *reinterpret_cast<const float4*>(bias + c + 4);

    float wgt[2][4];
    const __half* rp[2][4];

    #pragma unroll
    for (int pidx = 0; pidx < 2; pidx++) {
        const int n = n0 + pidx;
        const int b = bidx[n];
        const float px = centers[n * 3 + 0];
        const float py = centers[n * 3 + 1];
        const float pz = centers[n * 3 + 2];
        const float* tr = Tr + b * 16;
        const float* r0 = R0 + b * 16;
        const float* p2 = P2 + b * 12;

        float cam[4], rect[4], im[3];
        #pragma unroll
        for (int i = 0; i < 4; i++)
            cam[i] = tr[i*4+0]*px + tr[i*4+1]*py + tr[i*4+2]*pz + tr[i*4+3];
        #pragma unroll
        for (int i = 0; i < 4; i++)
            rect[i] = r0[i*4+0]*cam[0] + r0[i*4+1]*cam[1] + r0[i*4+2]*cam[2] + r0[i*4+3]*cam[3];
        #pragma unroll
        for (int i = 0; i < 3; i++)
            im[i] = p2[i*4+0]*rect[0] + p2[i*4+1]*rect[1] + p2[i*4+2]*rect[2] + p2[i*4+3]*rect[3];

        const float zc    = im[2];
        const float depth = fmaxf(zc, 1e-5f);
        const float u     = im[0] / depth;
        const float v     = im[1] / depth;
        const bool valid  = (zc > 0.f) && (u >= 0.f) && (u < (float)IMW) &&
                            (v >= 0.f) && (v < (float)IMH);

        const float x0f = floorf(u), y0f = floorf(v);
        const float wx1 = u - x0f, wx0 = 1.f - wx1;
        const float wy1 = v - y0f, wy0 = 1.f - wy1;
        const int xi0 = (int)x0f, yi0 = (int)y0f;
        const float cw[4] = {wx0 * wy0, wx1 * wy0, wx0 * wy1, wx1 * wy1};

        #pragma unroll
        for (int k = 0; k < 4; k++) {
            int xi = xi0 + (k & 1);
            int yi = yi0 + (k >> 1);
            bool inb = (xi >= 0) && (xi <= IMW - 1) && (yi >= 0) && (yi <= IMH - 1);
            wgt[pidx][k] = (valid && inb) ? cw[k] : 0.f;
            int xc = min(max(xi, 0), IMW - 1);
            int yc = min(max(yi, 0), IMH - 1);
            rp[pidx][k] = &g_pix[((size_t)((b * IMH + yc) * IMW + xc)) * CPT];
        }
    }

    // Batched loads: 8 pix corners + 2x2 pf rows in flight
    uint4 raw[2][4];
    #pragma unroll
    for (int pidx = 0; pidx < 2; pidx++)
        #pragma unroll
        for (int k = 0; k < 4; k++)
            raw[pidx][k] = *reinterpret_cast<const uint4*>(rp[pidx][k] + c);

    #pragma unroll
    for (int pidx = 0; pidx < 2; pidx++) {
        const int n = n0 + pidx;
        const float* pfrow = pf + (size_t)n * CPT + c;
        float4 pfv0 = *reinterpret_cast<const float4*>(pfrow);
        float4 pfv1 = *reinterpret_cast<const float4*>(pfrow + 4);

        float a[8];
        #pragma unroll
        for (int j = 0; j < 8; j++) a[j] = 0.f;
        #pragma unroll
        for (int k = 0; k < 4; k++) {
            const float w = wgt[pidx][k];
            const __half2* h = reinterpret_cast<const __half2*>(&raw[pidx][k]);
            #pragma unroll
            for (int j = 0; j < 4; j++) {
                float2 f = __half22float2(h[j]);
                a[2*j]   = fmaf(w, f.x, a[2*j]);
                a[2*j+1] = fmaf(w, f.y, a[2*j+1]);
            }
        }

        float* orow = out + (size_t)n * CPT + c;
        float4 o0, o1;
        o0.x = pfv0.x + (a[0] + bv0.x);
        o0.y = pfv0.y + (a[1] + bv0.y);
        o0.z = pfv0.z + (a[2] + bv0.z);
        o0.w = pfv0.w + (a[3] + bv0.w);
        o1.x = pfv1.x + (a[4] + bv1.x);
        o1.y = pfv1.y + (a[5] + bv1.y);
        o1.z = pfv1.z + (a[6] + bv1.z);
        o1.w = pfv1.w + (a[7] + bv1.w);
        *reinterpret_cast<float4*>(orow)     = o0;
        *reinterpret_cast<float4*>(orow + 4) = o1;
    }
}

// ---------------------------------------------------------------------------
// Launch
// ---------------------------------------------------------------------------
extern "C" void kernel_launch(void* const* d_in, const int* in_sizes, int n_in,
                              void* d_out, int out_size) {
    const float* point_feat = (const float*)d_in[0];
    const float* centers    = (const float*)d_in[1];
    const float* img_feat   = (const float*)d_in[2];
    const float* P2         = (const float*)d_in[3];
    const float* R0         = (const float*)d_in[4];
    const float* Tr         = (const float*)d_in[5];
    const float* align_w    = (const float*)d_in[6];
    const float* align_b    = (const float*)d_in[7];
    const int*   bidx       = (const int*)d_in[8];
    float* out = (float*)d_out;

    // Idempotent attribute set (not an allocation; safe under graph capture)
    cudaFuncSetAttribute(gemm_pix_kernel,
                         cudaFuncAttributeMaxDynamicSharedMemorySize, SMEM_TOTAL);

    convW_kernel<<<(CPT * CIMG + 255) / 256, 256>>>(align_w);
    gemm_pix_kernel<<<dim3(HW / BM, 1, BSZ), 256, SMEM_TOTAL>>>(img_feat);
    // 2 points per warp -> 16 points per 256-thread block
    fuse_kernel<<<(NPTS / 2 + 7) / 8, 256>>>(point_feat, centers, P2, R0, Tr, align_b, bidx, out);
}

// round 13
// speedup vs baseline: 1.5574x; 1.2190x over previous
#include <cuda_runtime.h>
#include <cuda_fp16.h>
#include <cstdint>

#define NPTS 100000
#define BSZ  8
#define CIMG 512
#define CPT  256
#define IMH  48
#define IMW  160
#define HW   (IMH*IMW)      /* 7680  */
#define NPIX (BSZ*HW)       /* 61440 */
#define NTILES 960          /* 64-pixel GEMM tiles: 8 batches x 120 */
#define TPB 120             /* tiles per batch */

// Scratch (device globals; no allocation in kernel_launch)
__device__ __half g_Wh[CPT * CIMG];                  // align_w in fp16, row-major (256,512)
__device__ __half g_pix[(size_t)NPIX * CPT];         // channel-last projected pixels, fp16
__device__ int    g_tileflags[NTILES];               // zeroed by compact_kernel each run
__device__ int    g_tilelist[NTILES];
__device__ int    g_tilecount;

// ---------------------------------------------------------------------------
// Shared projection helper (must match fuse_kernel semantics exactly)
// ---------------------------------------------------------------------------
__device__ __forceinline__ void project_point(
    int n, const float* __restrict__ centers,
    const float* __restrict__ P2, const float* __restrict__ R0,
    const float* __restrict__ Tr, const int* __restrict__ bidx,
    int& b_out, bool& valid, int& xi0, int& yi0,
    float& wx0, float& wx1, float& wy0, float& wy1)
{
    const int b = bidx[n];
    b_out = b;
    const float px = centers[n * 3 + 0];
    const float py = centers[n * 3 + 1];
    const float pz = centers[n * 3 + 2];
    const float* tr = Tr + b * 16;
    const float* r0 = R0 + b * 16;
    const float* p2 = P2 + b * 12;

    float cam[4], rect[4], im[3];
    #pragma unroll
    for (int i = 0; i < 4; i++)
        cam[i] = tr[i*4+0]*px + tr[i*4+1]*py + tr[i*4+2]*pz + tr[i*4+3];
    #pragma unroll
    for (int i = 0; i < 4; i++)
        rect[i] = r0[i*4+0]*cam[0] + r0[i*4+1]*cam[1] + r0[i*4+2]*cam[2] + r0[i*4+3]*cam[3];
    #pragma unroll
    for (int i = 0; i < 3; i++)
        im[i] = p2[i*4+0]*rect[0] + p2[i*4+1]*rect[1] + p2[i*4+2]*rect[2] + p2[i*4+3]*rect[3];

    const float zc    = im[2];
    const float depth = fmaxf(zc, 1e-5f);
    const float u     = im[0] / depth;
    const float v     = im[1] / depth;
    valid = (zc > 0.f) && (u >= 0.f) && (u < (float)IMW) && (v >= 0.f) && (v < (float)IMH);

    const float x0f = floorf(u), y0f = floorf(v);
    wx1 = u - x0f; wx0 = 1.f - wx1;
    wy1 = v - y0f; wy0 = 1.f - wy1;
    xi0 = (int)x0f; yi0 = (int)y0f;
}

// ---------------------------------------------------------------------------
// Kernel A: mark GEMM tiles touched by any point's (clamped) corners
// ---------------------------------------------------------------------------
__global__ void mask_kernel(const float* __restrict__ centers,
                            const float* __restrict__ P2,
                            const float* __restrict__ R0,
                            const float* __restrict__ Tr,
                            const int*   __restrict__ bidx) {
    __shared__ unsigned char sf[NTILES];
    const int tid = threadIdx.x;
    for (int i = tid; i < NTILES; i += 256) sf[i] = 0;
    __syncthreads();

    const int n = blockIdx.x * 256 + tid;
    if (n < NPTS) {
        int b, xi0, yi0; bool valid; float wx0, wx1, wy0, wy1;
        project_point(n, centers, P2, R0, Tr, bidx, b, valid, xi0, yi0, wx0, wx1, wy0, wy1);
        #pragma unroll
        for (int k = 0; k < 4; k++) {
            int xc = min(max(xi0 + (k & 1), 0), IMW - 1);
            int yc = min(max(yi0 + (k >> 1), 0), IMH - 1);
            int p  = yc * IMW + xc;
            sf[b * TPB + (p >> 6)] = 1;
        }
    }
    __syncthreads();
    for (int i = tid; i < NTILES; i += 256)
        if (sf[i]) g_tileflags[i] = 1;   // idempotent plain store; flags pre-zeroed
}

// ---------------------------------------------------------------------------
// Kernel B: compact active tiles into list + count, reset flags for next run
// ---------------------------------------------------------------------------
__global__ void compact_kernel() {
    __shared__ int cnt;
    const int tid = threadIdx.x;
    if (tid == 0) cnt = 0;
    __syncthreads();
    if (tid < NTILES && g_tileflags[tid]) {
        int p = atomicAdd(&cnt, 1);
        g_tilelist[p] = tid;
        g_tileflags[tid] = 0;            // ready for next graph replay
    }
    __syncthreads();
    if (tid == 0) g_tilecount = cnt;
}

// ---------------------------------------------------------------------------
// Kernel 0: convert align_w (f32) -> fp16
// ---------------------------------------------------------------------------
__global__ void convW_kernel(const float* __restrict__ W) {
    int i = blockIdx.x * blockDim.x + threadIdx.x;
    if (i < CPT * CIMG) g_Wh[i] = __float2half_rn(W[i]);
}

// ---------------------------------------------------------------------------
// Kernel 1: activity-masked GEMM over active 64-pixel tiles only.
//   cp.async 3-stage, BM=64 x BN=256, occ=2, convert-ahead Ah, x4 B-ldmatrix.
// ---------------------------------------------------------------------------
#define BM 64
#define BN 256
#define BK 32
#define STAGES 3

#define A_STAGE_F     (BK * BM)
#define B_ROW_H       (BK + 8)
#define B_STAGE_H     (BN * B_ROW_H)
#define AH_ROW_H      (BM + 8)
#define AH_STAGE_H    (BK * AH_ROW_H)
#define SMEM_TOTAL (STAGES * A_STAGE_F * 4 + STAGES * B_STAGE_H * 2 + 2 * AH_STAGE_H * 2)

__device__ __forceinline__ void cp16(void* s, const void* g) {
    uint32_t sa = (uint32_t)__cvta_generic_to_shared(s);
    asm volatile("cp.async.cg.shared.global [%0], [%1], 16;" :: "r"(sa), "l"(g));
}

__global__ __launch_bounds__(256, 2)
void gemm_pix_kernel(const float* __restrict__ img) {
    if ((int)blockIdx.x >= g_tilecount) return;
    const int tile = g_tilelist[blockIdx.x];
    const int b  = tile / TPB;
    const int p0 = (tile % TPB) * BM;

    extern __shared__ char smem_raw[];
    float*  Af = reinterpret_cast<float*>(smem_raw);
    __half* Bs = reinterpret_cast<__half*>(smem_raw + STAGES * A_STAGE_F * 4);
    __half* Ah = reinterpret_cast<__half*>(smem_raw + STAGES * A_STAGE_F * 4
                                           + STAGES * B_STAGE_H * 2);

    const float* gA = img + (size_t)b * CIMG * HW;

    const int tid  = threadIdx.x;
    const int lane = tid & 31;
    const int warp = tid >> 5;
    const int wm   = warp & 1;
    const int wn   = warp >> 1;

    float acc[2][8][4];
    #pragma unroll
    for (int i = 0; i < 2; i++)
        #pragma unroll
        for (int j = 0; j < 8; j++)
            #pragma unroll
            for (int k = 0; k < 4; k++) acc[i][j][k] = 0.f;

    int ak_[2], am_[2];
    #pragma unroll
    for (int i = 0; i < 2; i++) {
        int idx = tid + i * 256;
        ak_[i] = idx >> 4;
        am_[i] = (idx & 15) << 2;
    }

    #pragma unroll
    for (int s = 0; s < STAGES; s++) {
        const int kt = s * BK;
        #pragma unroll
        for (int i = 0; i < 2; i++)
            cp16(&Af[s * A_STAGE_F + ak_[i] * BM + am_[i]],
                 gA + (size_t)(kt + ak_[i]) * HW + p0 + am_[i]);
        #pragma unroll
        for (int i = 0; i < 4; i++) {
            int idx = tid + i * 256;
            int n = idx >> 2, kc = (idx & 3) << 3;
            cp16(&Bs[s * B_STAGE_H + n * B_ROW_H + kc],
                 &g_Wh[n * CIMG + kt + kc]);
        }
        asm volatile("cp.async.commit_group;");
    }

    asm volatile("cp.async.wait_group %0;" :: "n"(STAGES - 1));
    __syncthreads();
    #pragma unroll
    for (int i = 0; i < 2; i++) {
        float4 v = *reinterpret_cast<const float4*>(&Af[ak_[i] * BM + am_[i]]);
        __half2* dst = reinterpret_cast<__half2*>(&Ah[ak_[i] * AH_ROW_H + am_[i]]);
        dst[0] = __floats2half2_rn(v.x, v.y);
        dst[1] = __floats2half2_rn(v.z, v.w);
    }

    const int NT = CIMG / BK;   // 16
    for (int t = 0; t < NT; t++) {
        const int slot = t % STAGES;
        asm volatile("cp.async.wait_group %0;" :: "n"(1));
        __syncthreads();

        if (t + 1 < NT) {
            const int ns = (t + 1) % STAGES;
            const int na = (t + 1) & 1;
            #pragma unroll
            for (int i = 0; i < 2; i++) {
                float4 v = *reinterpret_cast<const float4*>(
                    &Af[ns * A_STAGE_F + ak_[i] * BM + am_[i]]);
                __half2* dst = reinterpret_cast<__half2*>(
                    &Ah[na * AH_STAGE_H + ak_[i] * AH_ROW_H + am_[i]]);
                dst[0] = __floats2half2_rn(v.x, v.y);
                dst[1] = __floats2half2_rn(v.z, v.w);
            }
        }

        const int ab = (t & 1) * AH_STAGE_H;
        #pragma unroll
        for (int ks = 0; ks < BK; ks += 16) {
            uint32_t af[2][4];
            uint32_t bfr[8][2];
            {
                int jj = lane >> 3, r = lane & 7;
                int m_off = (jj & 1) * 8, k_off = (jj >> 1) * 8;
                #pragma unroll
                for (int mt = 0; mt < 2; mt++) {
                    uint32_t addr = (uint32_t)__cvta_generic_to_shared(
                        &Ah[ab + (ks + k_off + r) * AH_ROW_H + wm * 32 + mt * 16 + m_off]);
                    asm volatile("ldmatrix.sync.aligned.m8n8.x4.trans.shared.b16 {%0,%1,%2,%3}, [%4];"
                                 : "=r"(af[mt][0]), "=r"(af[mt][1]), "=r"(af[mt][2]), "=r"(af[mt][3])
                                 : "r"(addr));
                }
                #pragma unroll
                for (int p = 0; p < 4; p++) {
                    uint32_t addr = (uint32_t)__cvta_generic_to_shared(
                        &Bs[slot * B_STAGE_H
                            + (wn * 64 + (p * 2 + (jj >> 1)) * 8 + r) * B_ROW_H
                            + ks + (jj & 1) * 8]);
                    asm volatile("ldmatrix.sync.aligned.m8n8.x4.shared.b16 {%0,%1,%2,%3}, [%4];"
                                 : "=r"(bfr[2*p][0]), "=r"(bfr[2*p][1]),
                                   "=r"(bfr[2*p+1][0]), "=r"(bfr[2*p+1][1])
                                 : "r"(addr));
                }
            }
            #pragma unroll
            for (int mt = 0; mt < 2; mt++)
                #pragma unroll
                for (int nt = 0; nt < 8; nt++) {
                    asm volatile("mma.sync.aligned.m16n8k16.row.col.f32.f16.f16.f32 "
                                 "{%0,%1,%2,%3}, {%4,%5,%6,%7}, {%8,%9}, {%0,%1,%2,%3};"
                                 : "+f"(acc[mt][nt][0]), "+f"(acc[mt][nt][1]),
                                   "+f"(acc[mt][nt][2]), "+f"(acc[mt][nt][3])
                                 : "r"(af[mt][0]), "r"(af[mt][1]), "r"(af[mt][2]), "r"(af[mt][3]),
                                   "r"(bfr[nt][0]), "r"(bfr[nt][1]));
                }
        }
        __syncthreads();

        if (t + STAGES < NT) {
            const int kt = (t + STAGES) * BK;
            #pragma unroll
            for (int i = 0; i < 2; i++)
                cp16(&Af[slot * A_STAGE_F + ak_[i] * BM + am_[i]],
                     gA + (size_t)(kt + ak_[i]) * HW + p0 + am_[i]);
            #pragma unroll
            for (int i = 0; i < 4; i++) {
                int idx = tid + i * 256;
                int n = idx >> 2, kc = (idx & 3) << 3;
                cp16(&Bs[slot * B_STAGE_H + n * B_ROW_H + kc],
                     &g_Wh[n * CIMG + kt + kc]);
            }
        }
        asm volatile("cp.async.commit_group;");
    }

    const int mrow = lane >> 2;
    const int ncol = (lane & 3) * 2;
    #pragma unroll
    for (int mt = 0; mt < 2; mt++) {
        #pragma unroll
        for (int nt = 0; nt < 8; nt++) {
            int m = wm * 32 + mt * 16 + mrow;
            int n = wn * 64 + nt * 8 + ncol;
            size_t base = ((size_t)(b * HW + p0 + m)) * CPT + n;
            *reinterpret_cast<__half2*>(&g_pix[base]) =
                __floats2half2_rn(acc[mt][nt][0], acc[mt][nt][1]);
            *reinterpret_cast<__half2*>(&g_pix[base + 8 * CPT]) =
                __floats2half2_rn(acc[mt][nt][2], acc[mt][nt][3]);
        }
    }
}

// ---------------------------------------------------------------------------
// Kernel 2: per-point projection + bilinear combine. TWO points per warp.
// ---------------------------------------------------------------------------
__global__ void fuse_kernel(const float* __restrict__ pf,
                            const float* __restrict__ centers,
                            const float* __restrict__ P2,
                            const float* __restrict__ R0,
                            const float* __restrict__ Tr,
                            const float* __restrict__ bias,
                            const int*   __restrict__ bidx,
                            float* __restrict__ out) {
    const int gw   = (blockIdx.x * blockDim.x + threadIdx.x) >> 5;
    const int lane = threadIdx.x & 31;
    const int n0   = gw * 2;
    if (n0 >= NPTS) return;

    const int c = lane * 8;
    float4 bv0 = *reinterpret_cast<const float4*>(bias + c);
    float4 bv1 = *reinterpret_cast<const float4*>(bias + c + 4);

    float wgt[2][4];
    const __half* rp[2][4];

    #pragma unroll
    for (int pidx = 0; pidx < 2; pidx++) {
        const int n = n0 + pidx;
        int b, xi0, yi0; bool valid; float wx0, wx1, wy0, wy1;
        project_point(n, centers, P2, R0, Tr, bidx, b, valid, xi0, yi0, wx0, wx1, wy0, wy1);
        const float cw[4] = {wx0 * wy0, wx1 * wy0, wx0 * wy1, wx1 * wy1};
        #pragma unroll
        for (int k = 0; k < 4; k++) {
            int xi = xi0 + (k & 1);
            int yi = yi0 + (k >> 1);
            bool inb = (xi >= 0) && (xi <= IMW - 1) && (yi >= 0) && (yi <= IMH - 1);
            wgt[pidx][k] = (valid && inb) ? cw[k] : 0.f;
            int xc = min(max(xi, 0), IMW - 1);
            int yc = min(max(yi, 0), IMH - 1);
            rp[pidx][k] = &g_pix[((size_t)((b * IMH + yc) * IMW + xc)) * CPT];
        }
    }

    uint4 raw[2][4];
    #pragma unroll
    for (int pidx = 0; pidx < 2; pidx++)
        #pragma unroll
        for (int k = 0; k < 4; k++)
            raw[pidx][k] = *reinterpret_cast<const uint4*>(rp[pidx][k] + c);

    #pragma unroll
    for (int pidx = 0; pidx < 2; pidx++) {
        const int n = n0 + pidx;
        const float* pfrow = pf + (size_t)n * CPT + c;
        float4 pfv0 = *reinterpret_cast<const float4*>(pfrow);
        float4 pfv1 = *reinterpret_cast<const float4*>(pfrow + 4);

        float a[8];
        #pragma unroll
        for (int j = 0; j < 8; j++) a[j] = 0.f;
        #pragma unroll
        for (int k = 0; k < 4; k++) {
            const float w = wgt[pidx][k];
            const __half2* h = reinterpret_cast<const __half2*>(&raw[pidx][k]);
            #pragma unroll
            for (int j = 0; j < 4; j++) {
                float2 f = __half22float2(h[j]);
                a[2*j]   = fmaf(w, f.x, a[2*j]);
                a[2*j+1] = fmaf(w, f.y, a[2*j+1]);
            }
        }

        float* orow = out + (size_t)n * CPT + c;
        float4 o0, o1;
        o0.x = pfv0.x + (a[0] + bv0.x);
        o0.y = pfv0.y + (a[1] + bv0.y);
        o0.z = pfv0.z + (a[2] + bv0.z);
        o0.w = pfv0.w + (a[3] + bv0.w);
        o1.x = pfv1.x + (a[4] + bv1.x);
        o1.y = pfv1.y + (a[5] + bv1.y);
        o1.z = pfv1.z + (a[6] + bv1.z);
        o1.w = pfv1.w + (a[7] + bv1.w);
        *reinterpret_cast<float4*>(orow)     = o0;
        *reinterpret_cast<float4*>(orow + 4) = o1;
    }
}

// ---------------------------------------------------------------------------
// Launch: convW | mask -> compact -> masked GEMM -> fuse
// ---------------------------------------------------------------------------
extern "C" void kernel_launch(void* const* d_in, const int* in_sizes, int n_in,
                              void* d_out, int out_size) {
    const float* point_feat = (const float*)d_in[0];
    const float* centers    = (const float*)d_in[1];
    const float* img_feat   = (const float*)d_in[2];
    const float* P2         = (const float*)d_in[3];
    const float* R0         = (const float*)d_in[4];
    const float* Tr         = (const float*)d_in[5];
    const float* align_w    = (const float*)d_in[6];
    const float* align_b    = (const float*)d_in[7];
    const int*   bidx       = (const int*)d_in[8];
    float* out = (float*)d_out;

    cudaFuncSetAttribute(gemm_pix_kernel,
                         cudaFuncAttributeMaxDynamicSharedMemorySize, SMEM_TOTAL);

    convW_kernel<<<(CPT * CIMG + 255) / 256, 256>>>(align_w);
    mask_kernel<<<(NPTS + 255) / 256, 256>>>(centers, P2, R0, Tr, bidx);
    compact_kernel<<<1, 1024>>>();
    gemm_pix_kernel<<<NTILES, 256, SMEM_TOTAL>>>(img_feat);
    fuse_kernel<<<(NPTS / 2 + 7) / 8, 256>>>(point_feat, centers, P2, R0, Tr, align_b, bidx, out);
}